// round 2
// baseline (speedup 1.0000x reference)
#include <cuda_runtime.h>
#include <math.h>

#define N_NODES 50000
#define N_EDGES 600000
#define IN_DIM  384
#define HID     128
#define HYP     256
#define EPSV    1e-10f

// ---------------- scratch (device globals; no allocation allowed) ----------------
__device__ float g_xemb[N_NODES * HID];
__device__ float g_acc [N_NODES * HID];
__device__ float g_curA[N_NODES * HID];
__device__ float g_curB[N_NODES * HID];
__device__ float g_Hm  [N_NODES * HYP];
__device__ float g_lat [HYP * HID];
__device__ float g_dinv[N_NODES];
__device__ float g_csr_val[N_EDGES];
__device__ int   g_csr_src[N_EDGES];
__device__ int   g_deg [N_NODES];
__device__ int   g_rowptr[N_NODES + 1];
__device__ int   g_fill[N_NODES];
__device__ int   g_part[64];

// ---------------- setup kernels ----------------
__global__ void k_zero() {
    int i = blockIdx.x * blockDim.x + threadIdx.x;
    if (i < N_NODES) { g_deg[i] = 0; g_fill[i] = 0; }
    if (i < HYP * HID) g_lat[i] = 0.f;
}

__global__ void k_deg(const int* __restrict__ dst) {
    int e = blockIdx.x * blockDim.x + threadIdx.x;
    if (e < N_EDGES) atomicAdd(&g_deg[dst[e]], 1);
}

__global__ void k_scan1() {
    __shared__ int sh[1024];
    int i = blockIdx.x * 1024 + threadIdx.x;
    int v = (i < N_NODES) ? g_deg[i] : 0;
    sh[threadIdx.x] = v;
    __syncthreads();
    for (int off = 1; off < 1024; off <<= 1) {
        int t = (threadIdx.x >= off) ? sh[threadIdx.x - off] : 0;
        __syncthreads();
        sh[threadIdx.x] += t;
        __syncthreads();
    }
    if (i < N_NODES) g_rowptr[i] = sh[threadIdx.x] - v;   // exclusive
    if (threadIdx.x == 1023) g_part[blockIdx.x] = sh[1023];
}

__global__ void k_scan2(int nb) {
    __shared__ int sh[64];
    int v = (threadIdx.x < nb) ? g_part[threadIdx.x] : 0;
    sh[threadIdx.x] = v;
    __syncthreads();
    for (int off = 1; off < 64; off <<= 1) {
        int t = (threadIdx.x >= off) ? sh[threadIdx.x - off] : 0;
        __syncthreads();
        sh[threadIdx.x] += t;
        __syncthreads();
    }
    if (threadIdx.x < nb) g_part[threadIdx.x] = sh[threadIdx.x] - v;
}

__global__ void k_scan3() {
    int i = blockIdx.x * 1024 + threadIdx.x;
    if (i < N_NODES) g_rowptr[i] += g_part[blockIdx.x];
}

__global__ void k_dinv() {
    int i = blockIdx.x * blockDim.x + threadIdx.x;
    if (i == 0) g_rowptr[N_NODES] = N_EDGES;
    if (i < N_NODES) {
        int d = g_deg[i];
        g_dinv[i] = (d > 0) ? rsqrtf((float)d) : 0.f;
    }
}

__global__ void k_fill(const int* __restrict__ src, const int* __restrict__ dst) {
    int e = blockIdx.x * blockDim.x + threadIdx.x;
    if (e < N_EDGES) {
        int d = dst[e], s = src[e];
        int pos = g_rowptr[d] + atomicAdd(&g_fill[d], 1);
        g_csr_src[pos] = s;
        g_csr_val[pos] = g_dinv[s] * g_dinv[d];
    }
}

// ---------------- G1: x_emb = x @ w_feat + b_feat ; acc = x_emb ----------------
// 64x128 tile, 256 threads, 8x4 per-thread register tile, K chunks of 16.
__global__ void k_gemm1(const float* __restrict__ x, const float* __restrict__ w,
                        const float* __restrict__ b) {
    __shared__ float As[16][64];
    __shared__ float Bs[16][128];
    int t  = threadIdx.x;
    int r0 = blockIdx.x * 64;
    int tn = t & 31, tm = t >> 5;
    int m0 = tm * 8, n0 = tn * 4;
    float acc[8][4];
#pragma unroll
    for (int j = 0; j < 8; j++)
#pragma unroll
        for (int i = 0; i < 4; i++) acc[j][i] = 0.f;

    int arow = t >> 2;
    int akk  = (t & 3) * 4;
    int grow = min(r0 + arow, N_NODES - 1);

    for (int k0 = 0; k0 < IN_DIM; k0 += 16) {
        float4 av = *(const float4*)(x + grow * IN_DIM + k0 + akk);
        As[akk + 0][arow] = av.x; As[akk + 1][arow] = av.y;
        As[akk + 2][arow] = av.z; As[akk + 3][arow] = av.w;
#pragma unroll
        for (int l = 0; l < 2; l++) {
            int f4 = t + l * 256;
            int kk = f4 >> 5, nc = (f4 & 31) << 2;
            *(float4*)&Bs[kk][nc] = *(const float4*)(w + (k0 + kk) * HID + nc);
        }
        __syncthreads();
#pragma unroll
        for (int kk = 0; kk < 16; kk++) {
            float a[8];
#pragma unroll
            for (int j = 0; j < 8; j++) a[j] = As[kk][m0 + j];
            float4 bv = *(const float4*)&Bs[kk][n0];
            float bb[4] = {bv.x, bv.y, bv.z, bv.w};
#pragma unroll
            for (int j = 0; j < 8; j++)
#pragma unroll
                for (int i = 0; i < 4; i++)
                    acc[j][i] = fmaf(a[j], bb[i], acc[j][i]);
        }
        __syncthreads();
    }
    float4 b4 = *(const float4*)(b + n0);
    float bb[4] = {b4.x, b4.y, b4.z, b4.w};
#pragma unroll
    for (int j = 0; j < 8; j++) {
        int row = r0 + m0 + j;
        if (row < N_NODES) {
            float4 ov;
            ov.x = acc[j][0] + bb[0]; ov.y = acc[j][1] + bb[1];
            ov.z = acc[j][2] + bb[2]; ov.w = acc[j][3] + bb[3];
            *(float4*)&g_xemb[row * HID + n0] = ov;
            *(float4*)&g_acc [row * HID + n0] = ov;
        }
    }
}

// ---------------- propagation: nxt[d] = sum_{e:dst=d} ew[e]*cur[src[e]] ; acc += nxt ---------
__global__ void k_prop(int step) {
    const float* cur = (step == 0) ? g_xemb : ((step == 1) ? g_curA : g_curB);
    float*       nxt = (step == 0) ? g_curA : ((step == 1) ? g_curB : g_curA);
    int d = blockIdx.x;
    int c = threadIdx.x;
    int s0 = g_rowptr[d], s1 = g_rowptr[d + 1];
    float sum = 0.f;
    for (int j = s0; j < s1; j++) {
        int   s = g_csr_src[j];
        float v = g_csr_val[j];
        sum = fmaf(cur[s * HID + c], v, sum);
    }
    nxt[d * HID + c] = sum;
    g_acc[d * HID + c] += sum;
}

// ---------------- Hm = softmax((x_emb @ w_hyper + gumbel)/tau) ----------------
// 64x256 tile, 256 threads, 8x8 per thread; softmax per row is warp-local.
__global__ void k_hyp(const float* __restrict__ wh, const float* __restrict__ u) {
    __shared__ float As[16][64];
    __shared__ float Bs[16][256];
    int t  = threadIdx.x;
    int r0 = blockIdx.x * 64;
    int tn = t & 31, tm = t >> 5;
    int m0 = tm * 8, n0 = tn * 8;
    float acc[8][8];
#pragma unroll
    for (int j = 0; j < 8; j++)
#pragma unroll
        for (int i = 0; i < 8; i++) acc[j][i] = 0.f;

    int arow = t >> 2;
    int akk  = (t & 3) * 4;
    int grow = min(r0 + arow, N_NODES - 1);

    for (int k0 = 0; k0 < HID; k0 += 16) {
        float4 av = *(const float4*)(g_xemb + grow * HID + k0 + akk);
        As[akk + 0][arow] = av.x; As[akk + 1][arow] = av.y;
        As[akk + 2][arow] = av.z; As[akk + 3][arow] = av.w;
#pragma unroll
        for (int l = 0; l < 4; l++) {
            int f4 = t + l * 256;
            int kk = f4 >> 6, nc = (f4 & 63) << 2;
            *(float4*)&Bs[kk][nc] = *(const float4*)(wh + (k0 + kk) * HYP + nc);
        }
        __syncthreads();
#pragma unroll
        for (int kk = 0; kk < 16; kk++) {
            float a[8];
#pragma unroll
            for (int j = 0; j < 8; j++) a[j] = As[kk][m0 + j];
            float bb[8];
            *(float4*)&bb[0] = *(const float4*)&Bs[kk][n0];
            *(float4*)&bb[4] = *(const float4*)&Bs[kk][n0 + 4];
#pragma unroll
            for (int j = 0; j < 8; j++)
#pragma unroll
                for (int i = 0; i < 8; i++)
                    acc[j][i] = fmaf(a[j], bb[i], acc[j][i]);
        }
        __syncthreads();
    }

#pragma unroll
    for (int j = 0; j < 8; j++) {
        int row   = r0 + m0 + j;                 // uniform within warp
        bool valid = row < N_NODES;
        int urow  = valid ? row : (N_NODES - 1);
        float4 u0 = *(const float4*)(u + urow * HYP + n0);
        float4 u1 = *(const float4*)(u + urow * HYP + n0 + 4);
        float uu[8] = {u0.x, u0.y, u0.z, u0.w, u1.x, u1.y, u1.z, u1.w};
        float tv[8];
        float mx = -1e30f;
#pragma unroll
        for (int i = 0; i < 8; i++) {
            float g = -logf(-logf(uu[i] + EPSV) + EPSV);
            tv[i] = (acc[j][i] + g) * 2.0f;      // /tau, tau=0.5
            mx = fmaxf(mx, tv[i]);
        }
#pragma unroll
        for (int o = 16; o >= 1; o >>= 1) mx = fmaxf(mx, __shfl_xor_sync(0xffffffffu, mx, o));
        float s = 0.f;
#pragma unroll
        for (int i = 0; i < 8; i++) { tv[i] = expf(tv[i] - mx); s += tv[i]; }
#pragma unroll
        for (int o = 16; o >= 1; o >>= 1) s += __shfl_xor_sync(0xffffffffu, s, o);
        float inv = 1.f / s;
        if (valid) {
            float4 o0, o1;
            o0.x = tv[0] * inv; o0.y = tv[1] * inv; o0.z = tv[2] * inv; o0.w = tv[3] * inv;
            o1.x = tv[4] * inv; o1.y = tv[5] * inv; o1.z = tv[6] * inv; o1.w = tv[7] * inv;
            *(float4*)&g_Hm[row * HYP + n0]     = o0;
            *(float4*)&g_Hm[row * HYP + n0 + 4] = o1;
        }
    }
}

// ---------------- lat = Hm^T @ x_emb   (split-K over rows, atomic reduce) ----------------
#define LAT_RPB 256
__global__ void k_lat() {
    __shared__ float hs[8 * 64];
    __shared__ float xs[8 * 128];
    int t = threadIdx.x;
    int c = t & 127;
    int g = t >> 7;                 // 0/1
    int hbase = blockIdx.y * 64;
    int h0 = g * 32;
    float acc[32];
#pragma unroll
    for (int i = 0; i < 32; i++) acc[i] = 0.f;

    int rstart = blockIdx.x * LAT_RPB;
    int rend   = min(rstart + LAT_RPB, N_NODES);
    for (int rb = rstart; rb < rend; rb += 8) {
        for (int i = t; i < 8 * 64; i += 256) {
            int r = i >> 6;
            hs[i] = (rb + r < rend) ? g_Hm[(rb + r) * HYP + hbase + (i & 63)] : 0.f;
        }
        for (int i = t; i < 8 * 128; i += 256) {
            int r = i >> 7;
            xs[i] = (rb + r < rend) ? g_xemb[(rb + r) * HID + (i & 127)] : 0.f;
        }
        __syncthreads();
#pragma unroll
        for (int r = 0; r < 8; r++) {
            float xv = xs[r * 128 + c];
#pragma unroll
            for (int i = 0; i < 32; i++)
                acc[i] = fmaf(hs[r * 64 + h0 + i], xv, acc[i]);
        }
        __syncthreads();
    }
#pragma unroll
    for (int i = 0; i < 32; i++)
        atomicAdd(&g_lat[(hbase + h0 + i) * HID + c], acc[i]);
}

// ---------------- hyper_out = Hm @ lat ; final = acc/4 + 0.1*normalize(hyper_out) ---------
__global__ void k_final(float* __restrict__ outF) {
    __shared__ float As[16][64];
    __shared__ float Bs[16][128];
    int t  = threadIdx.x;
    int r0 = blockIdx.x * 64;
    int tn = t & 31, tm = t >> 5;
    int m0 = tm * 8, n0 = tn * 4;
    float acc[8][4];
#pragma unroll
    for (int j = 0; j < 8; j++)
#pragma unroll
        for (int i = 0; i < 4; i++) acc[j][i] = 0.f;

    int arow = t >> 2;
    int akk  = (t & 3) * 4;
    int grow = min(r0 + arow, N_NODES - 1);

    for (int k0 = 0; k0 < HYP; k0 += 16) {
        float4 av = *(const float4*)(g_Hm + grow * HYP + k0 + akk);
        As[akk + 0][arow] = av.x; As[akk + 1][arow] = av.y;
        As[akk + 2][arow] = av.z; As[akk + 3][arow] = av.w;
#pragma unroll
        for (int l = 0; l < 2; l++) {
            int f4 = t + l * 256;
            int kk = f4 >> 5, nc = (f4 & 31) << 2;
            *(float4*)&Bs[kk][nc] = *(const float4*)(g_lat + (k0 + kk) * HID + nc);
        }
        __syncthreads();
#pragma unroll
        for (int kk = 0; kk < 16; kk++) {
            float a[8];
#pragma unroll
            for (int j = 0; j < 8; j++) a[j] = As[kk][m0 + j];
            float4 bv = *(const float4*)&Bs[kk][n0];
            float bb[4] = {bv.x, bv.y, bv.z, bv.w};
#pragma unroll
            for (int j = 0; j < 8; j++)
#pragma unroll
                for (int i = 0; i < 4; i++)
                    acc[j][i] = fmaf(a[j], bb[i], acc[j][i]);
        }
        __syncthreads();
    }

#pragma unroll
    for (int j = 0; j < 8; j++) {
        float ss = 0.f;
#pragma unroll
        for (int i = 0; i < 4; i++) ss += acc[j][i] * acc[j][i];
#pragma unroll
        for (int o = 16; o >= 1; o >>= 1) ss += __shfl_xor_sync(0xffffffffu, ss, o);
        float nrm = fmaxf(sqrtf(ss), 1e-12f);
        int row = r0 + m0 + j;
        if (row < N_NODES) {
            float inv = 0.1f / nrm;
            float4 ag = *(const float4*)&g_acc[row * HID + n0];
            float4 ov;
            ov.x = ag.x * 0.25f + acc[j][0] * inv;
            ov.y = ag.y * 0.25f + acc[j][1] * inv;
            ov.z = ag.z * 0.25f + acc[j][2] * inv;
            ov.w = ag.w * 0.25f + acc[j][3] * inv;
            *(float4*)&outF[row * HID + n0] = ov;
        }
    }
}

// ---------------- x_vision / x_text = relu(final @ W + b) (both in one kernel) ----------
__global__ void k_out(const float* __restrict__ fin,
                      const float* __restrict__ wv, const float* __restrict__ bv,
                      const float* __restrict__ wt, const float* __restrict__ bt,
                      float* __restrict__ vis, float* __restrict__ txt) {
    __shared__ float As[16][64];
    __shared__ float Bs[16][256];
    int t  = threadIdx.x;
    int r0 = blockIdx.x * 64;
    int tn = t & 31, tm = t >> 5;
    int m0 = tm * 8, n0 = tn * 8;
    float acc[8][8];
#pragma unroll
    for (int j = 0; j < 8; j++)
#pragma unroll
        for (int i = 0; i < 8; i++) acc[j][i] = 0.f;

    int arow = t >> 2;
    int akk  = (t & 3) * 4;
    int grow = min(r0 + arow, N_NODES - 1);

    for (int k0 = 0; k0 < HID; k0 += 16) {
        float4 av = *(const float4*)(fin + grow * HID + k0 + akk);
        As[akk + 0][arow] = av.x; As[akk + 1][arow] = av.y;
        As[akk + 2][arow] = av.z; As[akk + 3][arow] = av.w;
#pragma unroll
        for (int l = 0; l < 4; l++) {
            int f4 = t + l * 256;
            int kk = f4 >> 6, nc = (f4 & 63) << 2;
            const float* wsrc = (nc < 128) ? (wv + (k0 + kk) * HID + nc)
                                           : (wt + (k0 + kk) * HID + (nc - 128));
            *(float4*)&Bs[kk][nc] = *(const float4*)wsrc;
        }
        __syncthreads();
#pragma unroll
        for (int kk = 0; kk < 16; kk++) {
            float a[8];
#pragma unroll
            for (int j = 0; j < 8; j++) a[j] = As[kk][m0 + j];
            float bb[8];
            *(float4*)&bb[0] = *(const float4*)&Bs[kk][n0];
            *(float4*)&bb[4] = *(const float4*)&Bs[kk][n0 + 4];
#pragma unroll
            for (int j = 0; j < 8; j++)
#pragma unroll
                for (int i = 0; i < 8; i++)
                    acc[j][i] = fmaf(a[j], bb[i], acc[j][i]);
        }
        __syncthreads();
    }

    bool isv = (tn < 16);
    int cbase = isv ? n0 : (n0 - 128);
    const float* bias = isv ? bv : bt;
    float* o = isv ? vis : txt;
    float4 b0 = *(const float4*)(bias + cbase);
    float4 b1 = *(const float4*)(bias + cbase + 4);
    float bb[8] = {b0.x, b0.y, b0.z, b0.w, b1.x, b1.y, b1.z, b1.w};
#pragma unroll
    for (int j = 0; j < 8; j++) {
        int row = r0 + m0 + j;
        if (row < N_NODES) {
            float4 o0, o1;
            o0.x = fmaxf(acc[j][0] + bb[0], 0.f); o0.y = fmaxf(acc[j][1] + bb[1], 0.f);
            o0.z = fmaxf(acc[j][2] + bb[2], 0.f); o0.w = fmaxf(acc[j][3] + bb[3], 0.f);
            o1.x = fmaxf(acc[j][4] + bb[4], 0.f); o1.y = fmaxf(acc[j][5] + bb[5], 0.f);
            o1.z = fmaxf(acc[j][6] + bb[6], 0.f); o1.w = fmaxf(acc[j][7] + bb[7], 0.f);
            *(float4*)&o[row * HID + cbase]     = o0;
            *(float4*)&o[row * HID + cbase + 4] = o1;
        }
    }
}

// ---------------- launcher ----------------
extern "C" void kernel_launch(void* const* d_in, const int* in_sizes, int n_in,
                              void* d_out, int out_size) {
    const float* x       = (const float*)d_in[0];
    const int*   ei      = (const int*)  d_in[1];
    const float* u       = (const float*)d_in[2];
    const float* w_feat  = (const float*)d_in[3];
    const float* b_feat  = (const float*)d_in[4];
    const float* w_hyper = (const float*)d_in[5];
    const float* w_vis   = (const float*)d_in[6];
    const float* b_vis   = (const float*)d_in[7];
    const float* w_txt   = (const float*)d_in[8];
    const float* b_txt   = (const float*)d_in[9];

    float* out  = (float*)d_out;
    float* outF = out;
    float* outV = out + (size_t)N_NODES * HID;
    float* outT = out + (size_t)2 * N_NODES * HID;

    const int* src = ei;
    const int* dst = ei + N_EDGES;

    int nb = (N_NODES + 1023) / 1024;   // 49
    int gtile = (N_NODES + 63) / 64;    // 782

    k_zero <<<(N_NODES + 255) / 256, 256>>>();
    k_deg  <<<(N_EDGES + 255) / 256, 256>>>(dst);
    k_scan1<<<nb, 1024>>>();
    k_scan2<<<1, 64>>>(nb);
    k_scan3<<<nb, 1024>>>();
    k_dinv <<<(N_NODES + 255) / 256, 256>>>();
    k_fill <<<(N_EDGES + 255) / 256, 256>>>(src, dst);

    k_gemm1<<<gtile, 256>>>(x, w_feat, b_feat);

    k_prop<<<N_NODES, 128>>>(0);
    k_prop<<<N_NODES, 128>>>(1);
    k_prop<<<N_NODES, 128>>>(2);

    k_hyp<<<gtile, 256>>>(w_hyper, u);

    dim3 latgrid((N_NODES + LAT_RPB - 1) / LAT_RPB, 4);
    k_lat<<<latgrid, 256>>>();

    k_final<<<gtile, 256>>>(outF);
    k_out  <<<gtile, 256>>>(outF, w_vis, b_vis, w_txt, b_txt, outV, outT);
}

// round 3
// speedup vs baseline: 1.1652x; 1.1652x over previous
#include <cuda_runtime.h>
#include <math.h>
#include <stdint.h>

#define N_NODES 50000
#define N_EDGES 600000
#define IN_DIM  384
#define HID     128
#define HYP     256
#define EPSV    1e-10f
#define LATB    143          // split-K blocks for lat
#define NPB     352          // nodes per lat block (143*352 = 50336 >= 50000)

// ---------------- scratch (device globals; no allocation allowed) ----------------
__device__ float g_xemb[N_NODES * HID];
__device__ float g_acc [N_NODES * HID];
__device__ float g_curA[N_NODES * HID];
__device__ float g_curB[N_NODES * HID];
__device__ float g_Hm  [N_NODES * HYP];
__device__ float g_lat [HYP * HID];
__device__ float g_latP[LATB * HYP * HID];
__device__ float g_dinv[N_NODES];
__device__ float g_csr_val[N_EDGES];
__device__ int   g_csr_src[N_EDGES];
__device__ int   g_deg [N_NODES];
__device__ int   g_rowptr[N_NODES + 1];
__device__ int   g_fill[N_NODES];
__device__ int   g_part[64];

// ---------------- tf32 mma helpers ----------------
__device__ __forceinline__ uint32_t tf32c(float f) {
    uint32_t r;
    asm("cvt.rna.tf32.f32 %0, %1;" : "=r"(r) : "f"(f));
    return r;
}

__device__ __forceinline__ void mma8(float* c,
                                     uint32_t a0, uint32_t a1, uint32_t a2, uint32_t a3,
                                     uint32_t b0, uint32_t b1) {
    asm volatile(
        "mma.sync.aligned.m16n8k8.row.col.f32.tf32.tf32.f32 "
        "{%0,%1,%2,%3},{%4,%5,%6,%7},{%8,%9},{%0,%1,%2,%3};"
        : "+f"(c[0]), "+f"(c[1]), "+f"(c[2]), "+f"(c[3])
        : "r"(a0), "r"(a1), "r"(a2), "r"(a3), "r"(b0), "r"(b1));
}

// ---------------- setup kernels ----------------
__global__ void k_zero() {
    int i = blockIdx.x * blockDim.x + threadIdx.x;
    if (i < N_NODES) { g_deg[i] = 0; g_fill[i] = 0; }
}

__global__ void k_deg(const int* __restrict__ dst) {
    int e = blockIdx.x * blockDim.x + threadIdx.x;
    if (e < N_EDGES) atomicAdd(&g_deg[dst[e]], 1);
}

__global__ void k_scan1() {
    __shared__ int sh[1024];
    int i = blockIdx.x * 1024 + threadIdx.x;
    int v = (i < N_NODES) ? g_deg[i] : 0;
    sh[threadIdx.x] = v;
    __syncthreads();
    for (int off = 1; off < 1024; off <<= 1) {
        int t = (threadIdx.x >= off) ? sh[threadIdx.x - off] : 0;
        __syncthreads();
        sh[threadIdx.x] += t;
        __syncthreads();
    }
    if (i < N_NODES) g_rowptr[i] = sh[threadIdx.x] - v;
    if (threadIdx.x == 1023) g_part[blockIdx.x] = sh[1023];
}

__global__ void k_scan2(int nb) {
    __shared__ int sh[64];
    int v = (threadIdx.x < nb) ? g_part[threadIdx.x] : 0;
    sh[threadIdx.x] = v;
    __syncthreads();
    for (int off = 1; off < 64; off <<= 1) {
        int t = (threadIdx.x >= off) ? sh[threadIdx.x - off] : 0;
        __syncthreads();
        sh[threadIdx.x] += t;
        __syncthreads();
    }
    if (threadIdx.x < nb) g_part[threadIdx.x] = sh[threadIdx.x] - v;
}

__global__ void k_scan3() {
    int i = blockIdx.x * 1024 + threadIdx.x;
    if (i < N_NODES) g_rowptr[i] += g_part[blockIdx.x];
}

__global__ void k_dinv() {
    int i = blockIdx.x * blockDim.x + threadIdx.x;
    if (i == 0) g_rowptr[N_NODES] = N_EDGES;
    if (i < N_NODES) {
        int d = g_deg[i];
        g_dinv[i] = (d > 0) ? rsqrtf((float)d) : 0.f;
    }
}

__global__ void k_fill(const int* __restrict__ src, const int* __restrict__ dst) {
    int e = blockIdx.x * blockDim.x + threadIdx.x;
    if (e < N_EDGES) {
        int d = dst[e], s = src[e];
        int pos = g_rowptr[d] + atomicAdd(&g_fill[d], 1);
        g_csr_src[pos] = s;
        g_csr_val[pos] = g_dinv[s] * g_dinv[d];
    }
}

// ---------------- G1: x_emb = x @ w_feat + b_feat ; acc = x_emb (tf32 mma) ----------
// Tile M=128, N=128, K-chunk 16. 256 threads = 8 warps, warp w owns rows w*16..w*16+15.
__global__ __launch_bounds__(256) void k_gemm1(const float* __restrict__ x,
                                               const float* __restrict__ w,
                                               const float* __restrict__ b) {
    __shared__ float As[128 * 20];
    __shared__ float Bs[16 * 136];
    int t = threadIdx.x, lane = t & 31, wid = t >> 5;
    int g = lane >> 2, t4 = lane & 3;
    int r0 = blockIdx.x * 128, m0 = wid * 16;
    float acc[16][4];
#pragma unroll
    for (int n = 0; n < 16; n++) { acc[n][0] = acc[n][1] = acc[n][2] = acc[n][3] = 0.f; }

    for (int k0 = 0; k0 < IN_DIM; k0 += 16) {
        for (int i = t; i < 512; i += 256) {
            int row = i >> 2, c4 = (i & 3) * 4;
            int gr = min(r0 + row, N_NODES - 1);
            *(float4*)&As[row * 20 + c4] = *(const float4*)(x + (size_t)gr * IN_DIM + k0 + c4);
        }
        for (int i = t; i < 512; i += 256) {
            int row = i >> 5, c4 = (i & 31) * 4;
            *(float4*)&Bs[row * 136 + c4] = *(const float4*)(w + (k0 + row) * HID + c4);
        }
        __syncthreads();
#pragma unroll
        for (int ks = 0; ks < 2; ks++) {
            int ar = (m0 + g) * 20 + ks * 8 + t4;
            uint32_t a0 = tf32c(As[ar]),       a1 = tf32c(As[ar + 160]);
            uint32_t a2 = tf32c(As[ar + 4]),   a3 = tf32c(As[ar + 164]);
            const float* bp = &Bs[(ks * 8 + t4) * 136];
#pragma unroll
            for (int nt = 0; nt < 16; nt++)
                mma8(acc[nt], a0, a1, a2, a3, tf32c(bp[nt * 8 + g]), tf32c(bp[544 + nt * 8 + g]));
        }
        __syncthreads();
    }
    int rA = r0 + m0 + g, rB = rA + 8;
#pragma unroll
    for (int nt = 0; nt < 16; nt++) {
        int cn = nt * 8 + t4 * 2;
        float b0 = b[cn], b1 = b[cn + 1];
        if (rA < N_NODES) {
            float2 v = make_float2(acc[nt][0] + b0, acc[nt][1] + b1);
            *(float2*)&g_xemb[rA * HID + cn] = v;
            *(float2*)&g_acc [rA * HID + cn] = v;
        }
        if (rB < N_NODES) {
            float2 v = make_float2(acc[nt][2] + b0, acc[nt][3] + b1);
            *(float2*)&g_xemb[rB * HID + cn] = v;
            *(float2*)&g_acc [rB * HID + cn] = v;
        }
    }
}

// ---------------- propagation: nxt[d] = sum_{e:dst=d} ew[e]*cur[src[e]] ; acc += nxt ---------
__global__ void k_prop(int step) {
    const float* cur = (step == 0) ? g_xemb : ((step == 1) ? g_curA : g_curB);
    float*       nxt = (step == 0) ? g_curA : ((step == 1) ? g_curB : g_curA);
    int d = blockIdx.x;
    int c = threadIdx.x;
    int s0 = g_rowptr[d], s1 = g_rowptr[d + 1];
    float sum = 0.f;
    for (int j = s0; j < s1; j++) {
        int   s = g_csr_src[j];
        float v = g_csr_val[j];
        sum = fmaf(cur[s * HID + c], v, sum);
    }
    nxt[d * HID + c] = sum;
    g_acc[d * HID + c] += sum;
}

// ---------------- Hm = softmax((x_emb @ w_hyper + gumbel)*2) (tf32 mma, fused) ---------
// Tile M=128, N=256. 8 warps, each warp owns 16 rows x full 256 cols (32 n-tiles).
__global__ __launch_bounds__(256) void k_hyp(const float* __restrict__ wh,
                                             const float* __restrict__ u) {
    __shared__ float As[128 * 20];
    __shared__ float Bs[16 * 264];
    int t = threadIdx.x, lane = t & 31, wid = t >> 5;
    int g = lane >> 2, t4 = lane & 3;
    int r0 = blockIdx.x * 128, m0 = wid * 16;
    float acc[32][4];
#pragma unroll
    for (int n = 0; n < 32; n++) { acc[n][0] = acc[n][1] = acc[n][2] = acc[n][3] = 0.f; }

    for (int k0 = 0; k0 < HID; k0 += 16) {
        for (int i = t; i < 512; i += 256) {
            int row = i >> 2, c4 = (i & 3) * 4;
            int gr = min(r0 + row, N_NODES - 1);
            *(float4*)&As[row * 20 + c4] = *(const float4*)(g_xemb + (size_t)gr * HID + k0 + c4);
        }
        for (int i = t; i < 1024; i += 256) {
            int row = i >> 6, c4 = (i & 63) * 4;
            *(float4*)&Bs[row * 264 + c4] = *(const float4*)(wh + (k0 + row) * HYP + c4);
        }
        __syncthreads();
#pragma unroll
        for (int ks = 0; ks < 2; ks++) {
            int ar = (m0 + g) * 20 + ks * 8 + t4;
            uint32_t a0 = tf32c(As[ar]),       a1 = tf32c(As[ar + 160]);
            uint32_t a2 = tf32c(As[ar + 4]),   a3 = tf32c(As[ar + 164]);
            const float* bp = &Bs[(ks * 8 + t4) * 264];
#pragma unroll
            for (int nt = 0; nt < 32; nt++)
                mma8(acc[nt], a0, a1, a2, a3, tf32c(bp[nt * 8 + g]), tf32c(bp[1056 + nt * 8 + g]));
        }
        __syncthreads();
    }

    int rA = r0 + m0 + g, rB = rA + 8;
    int uA = min(rA, N_NODES - 1), uB = min(rB, N_NODES - 1);
    float mA = -1e30f, mB = -1e30f;
#pragma unroll
    for (int nt = 0; nt < 32; nt++) {
        int cn = nt * 8 + t4 * 2;
        float2 ua = *(const float2*)(u + (size_t)uA * HYP + cn);
        float2 ub = *(const float2*)(u + (size_t)uB * HYP + cn);
        acc[nt][0] = (acc[nt][0] - logf(-logf(ua.x + EPSV) + EPSV)) * 2.f;
        acc[nt][1] = (acc[nt][1] - logf(-logf(ua.y + EPSV) + EPSV)) * 2.f;
        acc[nt][2] = (acc[nt][2] - logf(-logf(ub.x + EPSV) + EPSV)) * 2.f;
        acc[nt][3] = (acc[nt][3] - logf(-logf(ub.y + EPSV) + EPSV)) * 2.f;
        mA = fmaxf(mA, fmaxf(acc[nt][0], acc[nt][1]));
        mB = fmaxf(mB, fmaxf(acc[nt][2], acc[nt][3]));
    }
    mA = fmaxf(mA, __shfl_xor_sync(0xffffffffu, mA, 1));
    mA = fmaxf(mA, __shfl_xor_sync(0xffffffffu, mA, 2));
    mB = fmaxf(mB, __shfl_xor_sync(0xffffffffu, mB, 1));
    mB = fmaxf(mB, __shfl_xor_sync(0xffffffffu, mB, 2));
    float sA = 0.f, sB = 0.f;
#pragma unroll
    for (int nt = 0; nt < 32; nt++) {
        acc[nt][0] = expf(acc[nt][0] - mA);
        acc[nt][1] = expf(acc[nt][1] - mA);
        acc[nt][2] = expf(acc[nt][2] - mB);
        acc[nt][3] = expf(acc[nt][3] - mB);
        sA += acc[nt][0] + acc[nt][1];
        sB += acc[nt][2] + acc[nt][3];
    }
    sA += __shfl_xor_sync(0xffffffffu, sA, 1);
    sA += __shfl_xor_sync(0xffffffffu, sA, 2);
    sB += __shfl_xor_sync(0xffffffffu, sB, 1);
    sB += __shfl_xor_sync(0xffffffffu, sB, 2);
    float iA = 1.f / sA, iB = 1.f / sB;
#pragma unroll
    for (int nt = 0; nt < 32; nt++) {
        int cn = nt * 8 + t4 * 2;
        if (rA < N_NODES)
            *(float2*)&g_Hm[(size_t)rA * HYP + cn] = make_float2(acc[nt][0] * iA, acc[nt][1] * iA);
        if (rB < N_NODES)
            *(float2*)&g_Hm[(size_t)rB * HYP + cn] = make_float2(acc[nt][2] * iB, acc[nt][3] * iB);
    }
}

// ---------------- lat partials: latP[b] = Hm[rows_b]^T @ xemb[rows_b] (tf32 mma) ------
// 512 threads = 16 warps, each warp owns 16 hyperedge rows x 128 hid cols.
__global__ __launch_bounds__(512) void k_lat() {
    __shared__ float Hs[16 * 264];
    __shared__ float Xs[16 * 136];
    int t = threadIdx.x, lane = t & 31, wid = t >> 5;
    int g = lane >> 2, t4 = lane & 3;
    int h0 = wid * 16;
    int base = blockIdx.x * NPB;
    float acc[16][4];
#pragma unroll
    for (int n = 0; n < 16; n++) { acc[n][0] = acc[n][1] = acc[n][2] = acc[n][3] = 0.f; }

    for (int c = 0; c < NPB; c += 16) {
        for (int i = t; i < 1024; i += 512) {
            int row = i >> 6, c4 = (i & 63) * 4;
            int node = base + c + row;
            float4 v = (node < N_NODES) ? *(const float4*)&g_Hm[(size_t)node * HYP + c4]
                                        : make_float4(0.f, 0.f, 0.f, 0.f);
            *(float4*)&Hs[row * 264 + c4] = v;
        }
        {
            int i = t;  // 512 float4, one per thread
            int row = i >> 5, c4 = (i & 31) * 4;
            int node = base + c + row;
            float4 v = (node < N_NODES) ? *(const float4*)&g_xemb[(size_t)node * HID + c4]
                                        : make_float4(0.f, 0.f, 0.f, 0.f);
            *(float4*)&Xs[row * 136 + c4] = v;
        }
        __syncthreads();
#pragma unroll
        for (int ks = 0; ks < 2; ks++) {
            const float* hp  = &Hs[(ks * 8 + t4) * 264];
            const float* hp4 = hp + 4 * 264;
            uint32_t a0 = tf32c(hp[h0 + g]),  a1 = tf32c(hp[h0 + g + 8]);
            uint32_t a2 = tf32c(hp4[h0 + g]), a3 = tf32c(hp4[h0 + g + 8]);
            const float* bp = &Xs[(ks * 8 + t4) * 136];
#pragma unroll
            for (int nt = 0; nt < 16; nt++)
                mma8(acc[nt], a0, a1, a2, a3, tf32c(bp[nt * 8 + g]), tf32c(bp[544 + nt * 8 + g]));
        }
        __syncthreads();
    }
    float* pb = &g_latP[(size_t)blockIdx.x * HYP * HID];
#pragma unroll
    for (int nt = 0; nt < 16; nt++) {
        int cn = nt * 8 + t4 * 2;
        *(float2*)&pb[(h0 + g) * HID + cn]     = make_float2(acc[nt][0], acc[nt][1]);
        *(float2*)&pb[(h0 + g + 8) * HID + cn] = make_float2(acc[nt][2], acc[nt][3]);
    }
}

__global__ void k_latred() {
    int i = blockIdx.x * blockDim.x + threadIdx.x;
    if (i < HYP * HID) {
        float s = 0.f;
        for (int b = 0; b < LATB; b++) s += g_latP[(size_t)b * HYP * HID + i];
        g_lat[i] = s;
    }
}

// ---------------- final = acc/4 + 0.1*normalize(Hm @ lat) (tf32 mma, fused) -----------
__global__ __launch_bounds__(256) void k_final(float* __restrict__ outF) {
    __shared__ float As[128 * 20];
    __shared__ float Bs[16 * 136];
    int t = threadIdx.x, lane = t & 31, wid = t >> 5;
    int g = lane >> 2, t4 = lane & 3;
    int r0 = blockIdx.x * 128, m0 = wid * 16;
    float acc[16][4];
#pragma unroll
    for (int n = 0; n < 16; n++) { acc[n][0] = acc[n][1] = acc[n][2] = acc[n][3] = 0.f; }

    for (int k0 = 0; k0 < HYP; k0 += 16) {
        for (int i = t; i < 512; i += 256) {
            int row = i >> 2, c4 = (i & 3) * 4;
            int gr = min(r0 + row, N_NODES - 1);
            *(float4*)&As[row * 20 + c4] = *(const float4*)(g_Hm + (size_t)gr * HYP + k0 + c4);
        }
        for (int i = t; i < 512; i += 256) {
            int row = i >> 5, c4 = (i & 31) * 4;
            *(float4*)&Bs[row * 136 + c4] = *(const float4*)(g_lat + (k0 + row) * HID + c4);
        }
        __syncthreads();
#pragma unroll
        for (int ks = 0; ks < 2; ks++) {
            int ar = (m0 + g) * 20 + ks * 8 + t4;
            uint32_t a0 = tf32c(As[ar]),       a1 = tf32c(As[ar + 160]);
            uint32_t a2 = tf32c(As[ar + 4]),   a3 = tf32c(As[ar + 164]);
            const float* bp = &Bs[(ks * 8 + t4) * 136];
#pragma unroll
            for (int nt = 0; nt < 16; nt++)
                mma8(acc[nt], a0, a1, a2, a3, tf32c(bp[nt * 8 + g]), tf32c(bp[544 + nt * 8 + g]));
        }
        __syncthreads();
    }

    float ssA = 0.f, ssB = 0.f;
#pragma unroll
    for (int nt = 0; nt < 16; nt++) {
        ssA += acc[nt][0] * acc[nt][0] + acc[nt][1] * acc[nt][1];
        ssB += acc[nt][2] * acc[nt][2] + acc[nt][3] * acc[nt][3];
    }
    ssA += __shfl_xor_sync(0xffffffffu, ssA, 1);
    ssA += __shfl_xor_sync(0xffffffffu, ssA, 2);
    ssB += __shfl_xor_sync(0xffffffffu, ssB, 1);
    ssB += __shfl_xor_sync(0xffffffffu, ssB, 2);
    float iA = 0.1f / fmaxf(sqrtf(ssA), 1e-12f);
    float iB = 0.1f / fmaxf(sqrtf(ssB), 1e-12f);
    int rA = r0 + m0 + g, rB = rA + 8;
#pragma unroll
    for (int nt = 0; nt < 16; nt++) {
        int cn = nt * 8 + t4 * 2;
        if (rA < N_NODES) {
            float2 ag = *(const float2*)&g_acc[rA * HID + cn];
            *(float2*)&outF[(size_t)rA * HID + cn] =
                make_float2(ag.x * 0.25f + acc[nt][0] * iA, ag.y * 0.25f + acc[nt][1] * iA);
        }
        if (rB < N_NODES) {
            float2 ag = *(const float2*)&g_acc[rB * HID + cn];
            *(float2*)&outF[(size_t)rB * HID + cn] =
                make_float2(ag.x * 0.25f + acc[nt][2] * iB, ag.y * 0.25f + acc[nt][3] * iB);
        }
    }
}

// ---------------- vis/txt = relu(final @ [wv|wt] + [bv|bt]) (tf32 mma) ----------------
// Tile M=64, N=256 (split: warps 0-3 cols 0-127 -> vis, warps 4-7 cols 128-255 -> txt).
__global__ __launch_bounds__(256) void k_out(const float* __restrict__ fin,
                                             const float* __restrict__ wv, const float* __restrict__ bv,
                                             const float* __restrict__ wt, const float* __restrict__ bt,
                                             float* __restrict__ vis, float* __restrict__ txt) {
    __shared__ float As[64 * 20];
    __shared__ float Bs[16 * 264];
    int t = threadIdx.x, lane = t & 31, wid = t >> 5;
    int g = lane >> 2, t4 = lane & 3;
    int mt = wid & 3, half = wid >> 2;
    int r0 = blockIdx.x * 64, m0 = mt * 16;
    float acc[16][4];
#pragma unroll
    for (int n = 0; n < 16; n++) { acc[n][0] = acc[n][1] = acc[n][2] = acc[n][3] = 0.f; }

    for (int k0 = 0; k0 < HID; k0 += 16) {
        {
            int i = t;  // 256 float4, one per thread
            int row = i >> 2, c4 = (i & 3) * 4;
            int gr = min(r0 + row, N_NODES - 1);
            *(float4*)&As[row * 20 + c4] = *(const float4*)(fin + (size_t)gr * HID + k0 + c4);
        }
        for (int i = t; i < 1024; i += 256) {
            int row = i >> 6, c4 = (i & 63) * 4;
            const float* srcp = (c4 < 128) ? (wv + (k0 + row) * HID + c4)
                                           : (wt + (k0 + row) * HID + (c4 - 128));
            *(float4*)&Bs[row * 264 + c4] = *(const float4*)srcp;
        }
        __syncthreads();
#pragma unroll
        for (int ks = 0; ks < 2; ks++) {
            int ar = (m0 + g) * 20 + ks * 8 + t4;
            uint32_t a0 = tf32c(As[ar]),       a1 = tf32c(As[ar + 160]);
            uint32_t a2 = tf32c(As[ar + 4]),   a3 = tf32c(As[ar + 164]);
            const float* bp = &Bs[(ks * 8 + t4) * 264 + half * 128];
#pragma unroll
            for (int nt = 0; nt < 16; nt++)
                mma8(acc[nt], a0, a1, a2, a3, tf32c(bp[nt * 8 + g]), tf32c(bp[1056 + nt * 8 + g]));
        }
        __syncthreads();
    }

    const float* bias = half ? bt : bv;
    float* o = half ? txt : vis;
    int rA = r0 + m0 + g, rB = rA + 8;
#pragma unroll
    for (int nt = 0; nt < 16; nt++) {
        int cn = nt * 8 + t4 * 2;
        float b0 = bias[cn], b1 = bias[cn + 1];
        if (rA < N_NODES)
            *(float2*)&o[(size_t)rA * HID + cn] =
                make_float2(fmaxf(acc[nt][0] + b0, 0.f), fmaxf(acc[nt][1] + b1, 0.f));
        if (rB < N_NODES)
            *(float2*)&o[(size_t)rB * HID + cn] =
                make_float2(fmaxf(acc[nt][2] + b0, 0.f), fmaxf(acc[nt][3] + b1, 0.f));
    }
}

// ---------------- launcher ----------------
extern "C" void kernel_launch(void* const* d_in, const int* in_sizes, int n_in,
                              void* d_out, int out_size) {
    const float* x       = (const float*)d_in[0];
    const int*   ei      = (const int*)  d_in[1];
    const float* u       = (const float*)d_in[2];
    const float* w_feat  = (const float*)d_in[3];
    const float* b_feat  = (const float*)d_in[4];
    const float* w_hyper = (const float*)d_in[5];
    const float* w_vis   = (const float*)d_in[6];
    const float* b_vis   = (const float*)d_in[7];
    const float* w_txt   = (const float*)d_in[8];
    const float* b_txt   = (const float*)d_in[9];

    float* out  = (float*)d_out;
    float* outF = out;
    float* outV = out + (size_t)N_NODES * HID;
    float* outT = out + (size_t)2 * N_NODES * HID;

    const int* src = ei;
    const int* dst = ei + N_EDGES;

    int nb = (N_NODES + 1023) / 1024;         // 49
    int g128 = (N_NODES + 127) / 128;         // 391
    int g64  = (N_NODES + 63) / 64;           // 782

    k_zero <<<(N_NODES + 255) / 256, 256>>>();
    k_deg  <<<(N_EDGES + 255) / 256, 256>>>(dst);
    k_scan1<<<nb, 1024>>>();
    k_scan2<<<1, 64>>>(nb);
    k_scan3<<<nb, 1024>>>();
    k_dinv <<<(N_NODES + 255) / 256, 256>>>();
    k_fill <<<(N_EDGES + 255) / 256, 256>>>(src, dst);

    k_gemm1<<<g128, 256>>>(x, w_feat, b_feat);

    k_prop<<<N_NODES, 128>>>(0);
    k_prop<<<N_NODES, 128>>>(1);
    k_prop<<<N_NODES, 128>>>(2);

    k_hyp<<<g128, 256>>>(w_hyper, u);

    k_lat<<<LATB, 512>>>();
    k_latred<<<(HYP * HID + 1023) / 1024, 1024>>>();

    k_final<<<g128, 256>>>(outF);
    k_out  <<<g64, 256>>>(outF, w_vis, b_vis, w_txt, b_txt, outV, outT);
}